// round 8
// baseline (speedup 1.0000x reference)
#include <cuda_runtime.h>
#include <cuda.h>
#include <cstdint>
#include <cstddef>

// Problem constants
#define NN    1024
#define FIN   64
#define NTHREADS 288          // 8 compute warps (4M x 2K-half, N=64 full) + 1 producer
#define TK    64
#define NST   3
#define NITER (NN / TK)       // 16

// ---- shared memory layout (floats) ----
// Pipeline: 3 stages x 16KB (x tile only: [64 nodes] x [2 halves x 32 feats], SW128)
#define STAGE_BYTES 16384
#define PIPE_FLOATS 12288                   // 3 * 4096
#define W1_BASE  12288                      // [64][136]  -> 20992
#define W2_BASE  20992                      // [128][72]  -> 30208
#define B1_BASE  30208
#define B2_BASE  30336
#define MBAR_FL  30400                      // 6 mbarriers (48B)
#define HS_BASE  30416                      // [128][68] = 8704 -> 39120
#define SMEM_FLOATS 39120                   // 156,480 bytes
#define TILE_BYTES 16384
// G overlays pipeline + W1 (both dead when G is written): [128][132] = 16896 < 20992
#define G_BASE   0

__device__ __forceinline__ unsigned f2tf(float f) {
    unsigned u;
    asm("cvt.rna.tf32.f32 %0, %1;" : "=r"(u) : "f"(f));
    return u;
}

__device__ __forceinline__ void mma8(float* c, const unsigned* a, const unsigned* b) {
    asm volatile(
        "mma.sync.aligned.m16n8k8.row.col.f32.tf32.tf32.f32 "
        "{%0,%1,%2,%3},{%4,%5,%6,%7},{%8,%9},{%0,%1,%2,%3};"
        : "+f"(c[0]), "+f"(c[1]), "+f"(c[2]), "+f"(c[3])
        : "r"(a[0]), "r"(a[1]), "r"(a[2]), "r"(a[3]), "r"(b[0]), "r"(b[1]));
}

__device__ __forceinline__ float4 ldcg4(const float* p) {
    float4 v;
    asm volatile("ld.global.cg.v4.f32 {%0,%1,%2,%3}, [%4];"
                 : "=f"(v.x), "=f"(v.y), "=f"(v.z), "=f"(v.w) : "l"(p));
    return v;
}

__device__ __forceinline__ void cp16(float* d, const float* s) {
    unsigned ds = (unsigned)__cvta_generic_to_shared(d);
    asm volatile("cp.async.cg.shared.global [%0], [%1], 16;" :: "r"(ds), "l"(s));
}
__device__ __forceinline__ void cpcommit() { asm volatile("cp.async.commit_group;"); }
template <int N> __device__ __forceinline__ void cpwait() {
    asm volatile("cp.async.wait_group %0;" :: "n"(N));
}

__device__ __forceinline__ void mbar_init(uint32_t mbar, uint32_t count) {
    asm volatile("mbarrier.init.shared.b64 [%0], %1;" :: "r"(mbar), "r"(count) : "memory");
}
__device__ __forceinline__ void mbar_expect_tx(uint32_t mbar, uint32_t bytes) {
    asm volatile("mbarrier.arrive.expect_tx.shared.b64 _, [%0], %1;" :: "r"(mbar), "r"(bytes) : "memory");
}
__device__ __forceinline__ void mbar_arrive(uint32_t mbar) {
    asm volatile("mbarrier.arrive.shared.b64 _, [%0];" :: "r"(mbar) : "memory");
}
__device__ __forceinline__ void mbar_wait(uint32_t mbar, uint32_t parity) {
    asm volatile(
        "{\n\t.reg .pred P;\n\t"
        "WL_%=:\n\t"
        "mbarrier.try_wait.parity.acquire.cta.shared::cta.b64 P, [%0], %1, 0x989680;\n\t"
        "@P bra.uni WD_%=;\n\t"
        "bra.uni WL_%=;\n\t"
        "WD_%=:\n\t}"
        :: "r"(mbar), "r"(parity) : "memory");
}

__device__ __forceinline__ void tma3d(uint32_t smem_dst, const CUtensorMap* map,
                                      int c0, int c1, int c2, uint32_t mbar) {
    asm volatile(
        "cp.async.bulk.tensor.3d.shared::cta.global.tile.mbarrier::complete_tx::bytes "
        "[%0], [%1, {%2, %3, %4}], [%5];"
        :: "r"(smem_dst), "l"(map), "r"(c0), "r"(c1), "r"(c2), "r"(mbar) : "memory");
}

extern __shared__ float sm[];

__global__ void __launch_bounds__(NTHREADS, 1) gin_fused_kernel(
    const __grid_constant__ CUtensorMap tma_x,
    const float* __restrict__ adj,
    const float* __restrict__ x,
    const unsigned char* __restrict__ mask,
    const float* __restrict__ W1, const float* __restrict__ b1,
    const float* __restrict__ W2, const float* __restrict__ b2,
    const float* __restrict__ eps, float* __restrict__ out)
{
    const int tid  = threadIdx.x;
    const int b    = blockIdx.x >> 3;
    const int m0   = (blockIdx.x & 7) * 128;
    const int lane = tid & 31;
    const int w    = tid >> 5;       // 0..8 ; warp 8 = producer
    const int wm   = w & 3;          // M strip (mainloop)
    const int kh   = (w >> 2) & 1;   // K-half (mainloop)
    const int lq   = lane >> 2;
    const int lr   = lane & 3;

    const float* adjbase = adj + ((size_t)b * NN + m0) * NN;
    const float* xb      = x + (size_t)b * NN * FIN;

    uint32_t smem_u32;
    asm("{ .reg .u64 t; cvta.to.shared.u64 t, %1; cvt.u32.u64 %0, t; }"
        : "=r"(smem_u32) : "l"(sm));
    const uint32_t mb_full0  = smem_u32 + MBAR_FL * 4;
    const uint32_t mb_empty0 = mb_full0 + 24;

    // ---------- inline mask-dtype probe (first 4 KB) ----------
    // mode: 0=int32, 1=uint8/bool, 2=float32
    int gt1 = 0, nzoff = 0;
    if (tid < 256) {
        uint4 u = ((const uint4*)mask)[tid];
        unsigned words[4] = {u.x, u.y, u.z, u.w};
        #pragma unroll
        for (int wi = 0; wi < 4; ++wi) {
            #pragma unroll
            for (int bi = 0; bi < 4; ++bi) {
                unsigned byte = (words[wi] >> (bi * 8)) & 0xFF;
                if (byte > 1) gt1 = 1;
                if (byte != 0 && ((wi * 4 + bi) & 3) != 0) nzoff = 1;
            }
        }
    }
    const int any_gt1   = __syncthreads_or(gt1);
    const int any_nzoff = __syncthreads_or(nzoff);
    const int mmode = any_gt1 ? 2 : (any_nzoff ? 1 : 0);

    // ---------- mbarrier init ----------
    if (tid == 0) {
        #pragma unroll
        for (int s = 0; s < NST; ++s) {
            mbar_init(mb_full0  + s * 8, 1);    // producer elect thread
            mbar_init(mb_empty0 + s * 8, 256);  // 8 compute warps
        }
    }

    // ---------- weights prologue (cp.async, waited after mainloop) ----------
    if (tid < 256) {
        #pragma unroll
        for (int t = 0; t < 8; ++t) {              // W1: 64x128 -> [64][136]
            int c = tid + t * 256;
            int r = c >> 5, cc = c & 31;
            cp16(sm + W1_BASE + r * 136 + cc * 4, W1 + r * 128 + cc * 4);
        }
        #pragma unroll
        for (int t = 0; t < 8; ++t) {              // W2: 128x64 -> [128][72]
            int c = tid + t * 256;
            int r = c >> 4, cc = c & 15;
            cp16(sm + W2_BASE + r * 72 + cc * 4, W2 + r * 64 + cc * 4);
        }
        if (tid < 32) cp16(sm + B1_BASE + tid * 4, b1 + tid * 4);
        if (tid < 16) cp16(sm + B2_BASE + tid * 4, b2 + tid * 4);
        cpcommit();
    }
    __syncthreads();   // mbar init visible before any TMA

    // ---------- GEMM1: agg = adj[b] @ x[b]  (M=128, N=64, K=1024) ----------
    // A streamed via LDG (no smem); B (x) via TMA ring. Warp: 32 M-rows, N=64, K-half 32.
    float acc[2][8][4];
    #pragma unroll
    for (int i = 0; i < 2; ++i)
        #pragma unroll
        for (int j = 0; j < 8; ++j)
            #pragma unroll
            for (int k = 0; k < 4; ++k) acc[i][j][k] = 0.f;

    if (w == 8) {
        if (lane == 0) {
            for (int it = 0; it < NITER; ++it) {
                const int s = it % NST, u = it / NST;
                if (it >= NST) mbar_wait(mb_empty0 + s * 8, (u - 1) & 1);
                const uint32_t full = mb_full0 + s * 8;
                mbar_expect_tx(full, TILE_BYTES);
                const uint32_t sb = smem_u32 + s * STAGE_BYTES;
                const int k0 = it * TK;
                tma3d(sb,        &tma_x, 0,  k0, b, full);  // feats 0-31
                tma3d(sb + 8192, &tma_x, 32, k0, b, full);  // feats 32-63
            }
        }
    } else {
        // A prefetch: P[mf*4 + h*2 + lohi], window-j layout (col = 4t+j)
        float4 Apf[2][8];
        auto loadA = [&](int it, float4* P) {
            const int kb = it * TK + kh * 32;
            #pragma unroll
            for (int mf = 0; mf < 2; ++mf)
                #pragma unroll
                for (int h = 0; h < 2; ++h) {
                    const float* rp = adjbase
                        + (size_t)(wm * 32 + mf * 16 + h * 8 + lq) * NN + kb + 4 * lr;
                    P[mf * 4 + h * 2 + 0] = ldcg4(rp);
                    P[mf * 4 + h * 2 + 1] = ldcg4(rp + 16);
                }
        };
        loadA(0, Apf[0]);

        #pragma unroll 2
        for (int it = 0; it < NITER; ++it) {
            const int buf = it & 1;
            if (it + 1 < NITER) loadA(it + 1, Apf[buf ^ 1]);

            const int s = it % NST, u = it / NST;
            mbar_wait(mb_full0 + s * 8, u & 1);
            const char* stage = (const char*)sm + s * STAGE_BYTES;

            const float4* P = Apf[buf];
            #pragma unroll
            for (int j = 0; j < 4; ++j) {
                // A fragments from prefetched registers (component j)
                unsigned a[2][4];
                #pragma unroll
                for (int mf = 0; mf < 2; ++mf) {
                    const float* lo0 = (const float*)&P[mf * 4 + 0];      // h0 lo
                    const float* hi0 = (const float*)&P[mf * 4 + 1];      // h0 hi
                    const float* lo1 = (const float*)&P[mf * 4 + 2];      // h1 lo
                    const float* hi1 = (const float*)&P[mf * 4 + 3];      // h1 hi
                    a[mf][0] = f2tf(lo0[j]);
                    a[mf][1] = f2tf(lo1[j]);
                    a[mf][2] = f2tf(hi0[j]);
                    a[mf][3] = f2tf(hi1[j]);
                }
                // B fragments: smem node rows (within tile) r1, r1+16
                const int r1 = kh * 32 + 4 * lr + j;
                const int r2 = r1 + 16;
                const uint32_t sw1 = (uint32_t)(r1 & 7) << 4;
                const uint32_t sw2 = (uint32_t)(r2 & 7) << 4;
                unsigned bb[8][2];
                #pragma unroll
                for (int nf = 0; nf < 8; ++nf) {
                    const int half = nf >> 2;
                    const uint32_t np = (uint32_t)((nf & 3) * 8 + lq) << 2;
                    const char* base = stage + half * 8192;
                    bb[nf][0] = f2tf(*(const float*)(base + r1 * 128 + (np ^ sw1)));
                    bb[nf][1] = f2tf(*(const float*)(base + r2 * 128 + (np ^ sw2)));
                }
                #pragma unroll
                for (int mf = 0; mf < 2; ++mf)
                    #pragma unroll
                    for (int nf = 0; nf < 8; ++nf)
                        mma8(acc[mf][nf], a[mf], bb[nf]);
            }
            mbar_arrive(mb_empty0 + s * 8);
        }
    }
    __syncthreads();   // mainloop fully done

    // ---------- epilogue 1: Hs = agg (K-half reduction) ----------
    float* Hs = sm + HS_BASE;  // [128][68]
    if (w < 4) {               // kh == 0 warps write
        #pragma unroll
        for (int mf = 0; mf < 2; ++mf) {
            int row = wm * 32 + mf * 16 + lq;
            #pragma unroll
            for (int nf = 0; nf < 8; ++nf) {
                int col = nf * 8 + lr * 2;
                Hs[row * 68 + col]           = acc[mf][nf][0];
                Hs[row * 68 + col + 1]       = acc[mf][nf][1];
                Hs[(row + 8) * 68 + col]     = acc[mf][nf][2];
                Hs[(row + 8) * 68 + col + 1] = acc[mf][nf][3];
            }
        }
    }
    __syncthreads();
    if (w >= 4 && w < 8) {     // kh == 1 warps accumulate
        #pragma unroll
        for (int mf = 0; mf < 2; ++mf) {
            int row = wm * 32 + mf * 16 + lq;
            #pragma unroll
            for (int nf = 0; nf < 8; ++nf) {
                int col = nf * 8 + lr * 2;
                Hs[row * 68 + col]           += acc[mf][nf][0];
                Hs[row * 68 + col + 1]       += acc[mf][nf][1];
                Hs[(row + 8) * 68 + col]     += acc[mf][nf][2];
                Hs[(row + 8) * 68 + col + 1] += acc[mf][nf][3];
            }
        }
    }
    __syncthreads();

    // Hs += (1+eps)*x  (vectorized from global)
    const float epsv = 1.0f + eps[0];
    if (tid < 256) {
        #pragma unroll
        for (int t = 0; t < 8; ++t) {
            int idx = tid + t * 256;          // 2048 float4 chunks
            int r = idx >> 4, c4 = idx & 15;
            float4 xv = ((const float4*)(xb + (size_t)(m0 + r) * FIN))[c4];
            float4* hp = (float4*)(Hs + r * 68 + c4 * 4);
            float4 hv = *hp;
            hv.x = fmaf(epsv, xv.x, hv.x);
            hv.y = fmaf(epsv, xv.y, hv.y);
            hv.z = fmaf(epsv, xv.z, hv.z);
            hv.w = fmaf(epsv, xv.w, hv.w);
            *hp = hv;
        }
        cpwait<0>();    // weights group done
    }
    __syncthreads();

    // ---------- GEMM2: G = relu(Hs @ W1 + b1)  (128x128, K=64), 8 warps 4x2 ----------
    const int ewm = w >> 1;     // 0..3 (epilogue M)
    const int ewn = w & 1;      // 0..1 (epilogue N)
    float* G = sm + G_BASE;     // [128][132] overlays pipeline+W1 (both dead after sync)
    float acc2[2][8][4];
    if (w < 8) {
        #pragma unroll
        for (int i = 0; i < 2; ++i)
            #pragma unroll
            for (int j = 0; j < 8; ++j)
                #pragma unroll
                for (int k = 0; k < 4; ++k) acc2[i][j][k] = 0.f;

        const float* W1s = sm + W1_BASE;  // [64][136]
        #pragma unroll
        for (int ks = 0; ks < 8; ++ks) {
            int kk = ks * 8;
            unsigned a[2][4], bb[8][2];
            #pragma unroll
            for (int mf = 0; mf < 2; ++mf) {
                const float* ap = Hs + (ewm * 32 + mf * 16 + lq) * 68 + kk + lr;
                a[mf][0] = f2tf(ap[0]);
                a[mf][1] = f2tf(ap[8 * 68]);
                a[mf][2] = f2tf(ap[4]);
                a[mf][3] = f2tf(ap[8 * 68 + 4]);
            }
            #pragma unroll
            for (int nf = 0; nf < 8; ++nf) {
                const float* bp = W1s + (kk + lr) * 136 + ewn * 64 + nf * 8 + lq;
                bb[nf][0] = f2tf(bp[0]);
                bb[nf][1] = f2tf(bp[4 * 136]);
            }
            #pragma unroll
            for (int mf = 0; mf < 2; ++mf)
                #pragma unroll
                for (int nf = 0; nf < 8; ++nf)
                    mma8(acc2[mf][nf], a[mf], bb[nf]);
        }
    }
    __syncthreads();   // all W1/pipeline reads done before G overlay writes

    if (w < 8) {
        const float* b1s = sm + B1_BASE;
        #pragma unroll
        for (int mf = 0; mf < 2; ++mf) {
            int row = ewm * 32 + mf * 16 + lq;
            #pragma unroll
            for (int nf = 0; nf < 8; ++nf) {
                int col = ewn * 64 + nf * 8 + lr * 2;
                float bv0 = b1s[col], bv1 = b1s[col + 1];
                G[row * 132 + col]           = fmaxf(acc2[mf][nf][0] + bv0, 0.f);
                G[row * 132 + col + 1]       = fmaxf(acc2[mf][nf][1] + bv1, 0.f);
                G[(row + 8) * 132 + col]     = fmaxf(acc2[mf][nf][2] + bv0, 0.f);
                G[(row + 8) * 132 + col + 1] = fmaxf(acc2[mf][nf][3] + bv1, 0.f);
            }
        }
    }
    __syncthreads();

    // ---------- GEMM3: out = G @ W2 + b2, masked  (128x64, K=128), 8 warps 4x2 ----------
    if (w < 8) {
        float acc3[2][4][4];
        #pragma unroll
        for (int i = 0; i < 2; ++i)
            #pragma unroll
            for (int j = 0; j < 4; ++j)
                #pragma unroll
                for (int k = 0; k < 4; ++k) acc3[i][j][k] = 0.f;

        const float* W2s = sm + W2_BASE;  // [128][72]
        #pragma unroll
        for (int ks = 0; ks < 16; ++ks) {
            int kk = ks * 8;
            unsigned a[2][4], bb[4][2];
            #pragma unroll
            for (int mf = 0; mf < 2; ++mf) {
                const float* ap = G + (ewm * 32 + mf * 16 + lq) * 132 + kk + lr;
                a[mf][0] = f2tf(ap[0]);
                a[mf][1] = f2tf(ap[8 * 132]);
                a[mf][2] = f2tf(ap[4]);
                a[mf][3] = f2tf(ap[8 * 132 + 4]);
            }
            #pragma unroll
            for (int nf = 0; nf < 4; ++nf) {
                const float* bp = W2s + (kk + lr) * 72 + ewn * 32 + nf * 8 + lq;
                bb[nf][0] = f2tf(bp[0]);
                bb[nf][1] = f2tf(bp[4 * 72]);
            }
            #pragma unroll
            for (int mf = 0; mf < 2; ++mf)
                #pragma unroll
                for (int nf = 0; nf < 4; ++nf)
                    mma8(acc3[mf][nf], a[mf], bb[nf]);
        }

        auto mask_at = [&](int idx) -> bool {
            if (mmode == 0) return ((const int*)mask)[idx] != 0;
            if (mmode == 2) return ((const float*)mask)[idx] != 0.0f;
            return mask[idx] != 0;
        };

        const float* b2s = sm + B2_BASE;
        #pragma unroll
        for (int mf = 0; mf < 2; ++mf) {
            int row  = ewm * 32 + mf * 16 + lq;
            int grow = m0 + row;
            bool mk0 = mask_at(b * NN + grow);
            bool mk1 = mask_at(b * NN + grow + 8);
            #pragma unroll
            for (int nf = 0; nf < 4; ++nf) {
                int col = ewn * 32 + nf * 8 + lr * 2;
                float bv0 = b2s[col], bv1 = b2s[col + 1];
                float o0 = acc3[mf][nf][0] + bv0;
                float o1 = acc3[mf][nf][1] + bv1;
                float o2 = acc3[mf][nf][2] + bv0;
                float o3 = acc3[mf][nf][3] + bv1;
                float2* op0 = (float2*)(out + ((size_t)b * NN + grow) * 64 + col);
                float2* op1 = (float2*)(out + ((size_t)b * NN + grow + 8) * 64 + col);
                *op0 = mk0 ? make_float2(o0, o1) : make_float2(0.f, 0.f);
                *op1 = mk1 ? make_float2(o2, o3) : make_float2(0.f, 0.f);
            }
        }
    }
}

// ---- host side ----
typedef CUresult (*PFN_encodeTiled)(
    CUtensorMap*, CUtensorMapDataType, cuuint32_t, void*,
    const cuuint64_t*, const cuuint64_t*, const cuuint32_t*, const cuuint32_t*,
    CUtensorMapInterleave, CUtensorMapSwizzle, CUtensorMapL2promotion,
    CUtensorMapFloatOOBfill);

extern "C" void kernel_launch(void* const* d_in, const int* in_sizes, int n_in,
                              void* d_out, int out_size)
{
    // Identify inputs by element count (robust to metadata ordering).
    const float *x = 0, *adj = 0, *W1 = 0, *W2 = 0, *b1 = 0, *b2 = 0, *eps = 0;
    const unsigned char* mask = 0;
    for (int i = 0; i < n_in; ++i) {
        switch (in_sizes[i]) {
            case 64 * 1024 * 64:   x    = (const float*)d_in[i]; break;
            case 64 * 1024 * 1024: adj  = (const float*)d_in[i]; break;
            case 64 * 1024:        mask = (const unsigned char*)d_in[i]; break;
            case 64 * 128:         if (!W1) W1 = (const float*)d_in[i];
                                   else     W2 = (const float*)d_in[i]; break;
            case 128:              b1   = (const float*)d_in[i]; break;
            case 64:               b2   = (const float*)d_in[i]; break;
            case 1:                eps  = (const float*)d_in[i]; break;
            default: break;
        }
    }
    float* out = (float*)d_out;

    // Driver entry point via runtime API (no -lcuda link needed).
    static PFN_encodeTiled encode = nullptr;
    if (!encode) {
        void* fp = nullptr;
        cudaDriverEntryPointQueryResult qr;
        cudaGetDriverEntryPoint("cuTensorMapEncodeTiled", &fp, cudaEnableDefault, &qr);
        encode = (PFN_encodeTiled)fp;
    }

    CUtensorMap tm_x{};
    {
        cuuint64_t dims[3]    = {64, 1024, 64};
        cuuint64_t strides[2] = {64ull * 4, 1024ull * 64 * 4};
        cuuint32_t box[3]     = {32, 64, 1};
        cuuint32_t es[3]      = {1, 1, 1};
        encode(&tm_x, CU_TENSOR_MAP_DATA_TYPE_FLOAT32, 3, (void*)x,
               dims, strides, box, es,
               CU_TENSOR_MAP_INTERLEAVE_NONE, CU_TENSOR_MAP_SWIZZLE_128B,
               CU_TENSOR_MAP_L2_PROMOTION_L2_128B, CU_TENSOR_MAP_FLOAT_OOB_FILL_NONE);
    }

    cudaFuncSetAttribute(gin_fused_kernel,
                         cudaFuncAttributeMaxDynamicSharedMemorySize,
                         SMEM_FLOATS * (int)sizeof(float));
    gin_fused_kernel<<<512, NTHREADS, SMEM_FLOATS * sizeof(float)>>>(
        tm_x, adj, x, mask, W1, b1, W2, b2, eps, out);
}

// round 9
// speedup vs baseline: 1.2576x; 1.2576x over previous
#include <cuda_runtime.h>
#include <cuda.h>
#include <cstdint>
#include <cstddef>

// Problem constants
#define NN    1024
#define FIN   64
#define NTHREADS 544          // 16 compute warps (2 groups x [4M x 2N]) + 1 producer
#define TK    64
#define NST   3
#define NITER (NN / TK)       // 16

// ---- shared memory layout (floats) ----
// Ring: 3 stages x 48KB. Stage: adj k-half0 16KB | adj k-half1 16KB | x n-half0 8KB | x n-half1 8KB
#define STAGE_BYTES   49152
#define W1_BASE  36864                      // [64][136]
#define W2_BASE  45568                      // [128][72]
#define B1_BASE  54784
#define B2_BASE  54912
#define MBAR_FL  54976                      // 6 mbarriers (48B)
#define SMEM_FLOATS 54988                   // 219,952 bytes
#define TILE_BYTES 49152
// Post-mainloop overlays (ring dead):
#define HS_BASE 0                           // [128][68] = 8704 floats
#define G_BASE  8704                        // [128][132] = 16896 -> 25600 < 36864

__device__ __forceinline__ unsigned f2tf(float f) {
    unsigned u;
    asm("cvt.rna.tf32.f32 %0, %1;" : "=r"(u) : "f"(f));
    return u;
}

__device__ __forceinline__ void mma8(float* c, const unsigned* a, const unsigned* b) {
    asm volatile(
        "mma.sync.aligned.m16n8k8.row.col.f32.tf32.tf32.f32 "
        "{%0,%1,%2,%3},{%4,%5,%6,%7},{%8,%9},{%0,%1,%2,%3};"
        : "+f"(c[0]), "+f"(c[1]), "+f"(c[2]), "+f"(c[3])
        : "r"(a[0]), "r"(a[1]), "r"(a[2]), "r"(a[3]), "r"(b[0]), "r"(b[1]));
}

__device__ __forceinline__ void cp16(float* d, const float* s) {
    unsigned ds = (unsigned)__cvta_generic_to_shared(d);
    asm volatile("cp.async.cg.shared.global [%0], [%1], 16;" :: "r"(ds), "l"(s));
}
__device__ __forceinline__ void cpcommit() { asm volatile("cp.async.commit_group;"); }
template <int N> __device__ __forceinline__ void cpwait() {
    asm volatile("cp.async.wait_group %0;" :: "n"(N));
}

__device__ __forceinline__ void mbar_init(uint32_t mbar, uint32_t count) {
    asm volatile("mbarrier.init.shared.b64 [%0], %1;" :: "r"(mbar), "r"(count) : "memory");
}
__device__ __forceinline__ void mbar_expect_tx(uint32_t mbar, uint32_t bytes) {
    asm volatile("mbarrier.arrive.expect_tx.shared.b64 _, [%0], %1;" :: "r"(mbar), "r"(bytes) : "memory");
}
__device__ __forceinline__ void mbar_arrive(uint32_t mbar) {
    asm volatile("mbarrier.arrive.shared.b64 _, [%0];" :: "r"(mbar) : "memory");
}
__device__ __forceinline__ void mbar_wait(uint32_t mbar, uint32_t parity) {
    asm volatile(
        "{\n\t.reg .pred P;\n\t"
        "WL_%=:\n\t"
        "mbarrier.try_wait.parity.acquire.cta.shared::cta.b64 P, [%0], %1, 0x989680;\n\t"
        "@P bra.uni WD_%=;\n\t"
        "bra.uni WL_%=;\n\t"
        "WD_%=:\n\t}"
        :: "r"(mbar), "r"(parity) : "memory");
}

__device__ __forceinline__ void tma3d(uint32_t smem_dst, const CUtensorMap* map,
                                      int c0, int c1, int c2, uint32_t mbar) {
    asm volatile(
        "cp.async.bulk.tensor.3d.shared::cta.global.tile.mbarrier::complete_tx::bytes "
        "[%0], [%1, {%2, %3, %4}], [%5];"
        :: "r"(smem_dst), "l"(map), "r"(c0), "r"(c1), "r"(c2), "r"(mbar) : "memory");
}

extern __shared__ float sm[];

__global__ void __launch_bounds__(NTHREADS, 1) gin_fused_kernel(
    const __grid_constant__ CUtensorMap tma_adj,
    const __grid_constant__ CUtensorMap tma_x,
    const float* __restrict__ x,
    const unsigned char* __restrict__ mask,
    const float* __restrict__ W1, const float* __restrict__ b1,
    const float* __restrict__ W2, const float* __restrict__ b2,
    const float* __restrict__ eps, float* __restrict__ out)
{
    const int tid  = threadIdx.x;
    const int b    = blockIdx.x >> 3;
    const int m0   = (blockIdx.x & 7) * 128;
    const int lane = tid & 31;
    const int w    = tid >> 5;       // 0..16 ; warp 16 = producer
    const int wm   = w & 3;          // M strip (all phases)
    const int wn   = (w >> 2) & 1;   // N half (mainloop, within group)
    const int grp  = (w >> 3) & 1;   // consumer group: iters it ≡ grp (mod 2)
    const int wq   = w >> 2;         // 0..3 N direction (epilogue GEMMs, w<16)
    const int lq   = lane >> 2;
    const int lr   = lane & 3;

    const float* xb = x + (size_t)b * NN * FIN;

    uint32_t smem_u32;
    asm("{ .reg .u64 t; cvta.to.shared.u64 t, %1; cvt.u32.u64 %0, t; }"
        : "=r"(smem_u32) : "l"(sm));
    const uint32_t mb_full0  = smem_u32 + MBAR_FL * 4;
    const uint32_t mb_empty0 = mb_full0 + 24;

    // ---------- inline mask-dtype probe (first 4 KB) ----------
    // mode: 0=int32, 1=uint8/bool, 2=float32
    int gt1 = 0, nzoff = 0;
    if (tid < 256) {
        uint4 u = ((const uint4*)mask)[tid];
        unsigned words[4] = {u.x, u.y, u.z, u.w};
        #pragma unroll
        for (int wi = 0; wi < 4; ++wi) {
            #pragma unroll
            for (int bi = 0; bi < 4; ++bi) {
                unsigned byte = (words[wi] >> (bi * 8)) & 0xFF;
                if (byte > 1) gt1 = 1;
                if (byte != 0 && ((wi * 4 + bi) & 3) != 0) nzoff = 1;
            }
        }
    }
    const int any_gt1   = __syncthreads_or(gt1);
    const int any_nzoff = __syncthreads_or(nzoff);
    const int mmode = any_gt1 ? 2 : (any_nzoff ? 1 : 0);

    // ---------- mbarrier init ----------
    if (tid == 0) {
        #pragma unroll
        for (int s = 0; s < NST; ++s) {
            mbar_init(mb_full0  + s * 8, 1);    // producer elect thread
            mbar_init(mb_empty0 + s * 8, 256);  // exactly one 8-warp group consumes each stage instance
        }
    }

    // ---------- weights prologue (cp.async, waited after mainloop) ----------
    if (tid < 256) {
        #pragma unroll
        for (int t = 0; t < 8; ++t) {              // W1: 64x128 -> [64][136]
            int c = tid + t * 256;
            int r = c >> 5, cc = c & 31;
            cp16(sm + W1_BASE + r * 136 + cc * 4, W1 + r * 128 + cc * 4);
        }
        #pragma unroll
        for (int t = 0; t < 8; ++t) {              // W2: 128x64 -> [128][72]
            int c = tid + t * 256;
            int r = c >> 4, cc = c & 15;
            cp16(sm + W2_BASE + r * 72 + cc * 4, W2 + r * 64 + cc * 4);
        }
        if (tid < 32) cp16(sm + B1_BASE + tid * 4, b1 + tid * 4);
        if (tid < 16) cp16(sm + B2_BASE + tid * 4, b2 + tid * 4);
        cpcommit();
    }
    __syncthreads();   // mbar init visible before any TMA

    // ---------- GEMM1: agg = adj[b] @ x[b]  (M=128, N=64, K=1024) ----------
    // Group grp consumes iterations it ≡ grp (mod 2); each accumulates half of K.
    float acc[2][4][4];
    #pragma unroll
    for (int i = 0; i < 2; ++i)
        #pragma unroll
        for (int j = 0; j < 4; ++j)
            #pragma unroll
            for (int k = 0; k < 4; ++k) acc[i][j][k] = 0.f;

    if (w == 16) {
        if (lane == 0) {
            for (int it = 0; it < NITER; ++it) {
                const int s = it % NST, u = it / NST;
                if (it >= NST) mbar_wait(mb_empty0 + s * 8, (u - 1) & 1);
                const uint32_t full = mb_full0 + s * 8;
                mbar_expect_tx(full, TILE_BYTES);
                const uint32_t sb = smem_u32 + s * STAGE_BYTES;
                const int k0 = it * TK;
                tma3d(sb,         &tma_adj, k0,      m0, b, full);  // adj k-half 0
                tma3d(sb + 16384, &tma_adj, k0 + 32, m0, b, full);  // adj k-half 1
                tma3d(sb + 32768, &tma_x,   0,       k0, b, full);  // x  n-half 0
                tma3d(sb + 40960, &tma_x,   32,      k0, b, full);  // x  n-half 1
            }
        }
    } else {
        const uint32_t xorA = (uint32_t)lq << 4;   // SW128: row%8 == lq
        for (int it = grp; it < NITER; it += 2) {
            const int s = it % NST, u = it / NST;
            mbar_wait(mb_full0 + s * 8, u & 1);

            const char* stage = (const char*)sm + s * STAGE_BYTES;
            const char* Bh    = stage + 32768 + wn * 8192;  // this warp's x n-half
            #pragma unroll
            for (int ks = 0; ks < TK / 8; ++ks) {
                const int kk = ks * 8;
                const char* Ah = stage + ((kk >> 5) << 14);  // 16KB per adj k-half
                const int kl = (kk & 31) + lr;
                unsigned a[2][4], bb[4][2];
                #pragma unroll
                for (int mf = 0; mf < 2; ++mf) {
                    const uint32_t r0 = (uint32_t)(wm * 32 + mf * 16 + lq) * 128;
                    const uint32_t r1 = r0 + 8 * 128;
                    a[mf][0] = f2tf(*(const float*)(Ah + r0 + (((uint32_t)kl << 2) ^ xorA)));
                    a[mf][1] = f2tf(*(const float*)(Ah + r1 + (((uint32_t)kl << 2) ^ xorA)));
                    a[mf][2] = f2tf(*(const float*)(Ah + r0 + (((uint32_t)(kl + 4) << 2) ^ xorA)));
                    a[mf][3] = f2tf(*(const float*)(Ah + r1 + (((uint32_t)(kl + 4) << 2) ^ xorA)));
                }
                const uint32_t kr0 = (uint32_t)(kk + lr) * 128;
                const uint32_t kr1 = kr0 + 4 * 128;
                const uint32_t xb0 = (uint32_t)lr << 4;
                const uint32_t xb1 = (uint32_t)(lr + 4) << 4;
                #pragma unroll
                for (int nf = 0; nf < 4; ++nf) {
                    const uint32_t nl = (uint32_t)(nf * 8 + lq) << 2;
                    bb[nf][0] = f2tf(*(const float*)(Bh + kr0 + (nl ^ xb0)));
                    bb[nf][1] = f2tf(*(const float*)(Bh + kr1 + (nl ^ xb1)));
                }
                #pragma unroll
                for (int mf = 0; mf < 2; ++mf)
                    #pragma unroll
                    for (int nf = 0; nf < 4; ++nf)
                        mma8(acc[mf][nf], a[mf], bb[nf]);
            }
            mbar_arrive(mb_empty0 + s * 8);
        }
    }
    __syncthreads();   // ring fully drained; safe to overlay

    // ---------- epilogue 1: Hs = agg (group reduction), then += (1+eps)*x ----------
    float* Hs = sm + HS_BASE;  // [128][68]
    if (w < 8) {               // group 0 writes
        #pragma unroll
        for (int mf = 0; mf < 2; ++mf) {
            int row = wm * 32 + mf * 16 + lq;
            #pragma unroll
            for (int nf = 0; nf < 4; ++nf) {
                int col = wn * 32 + nf * 8 + lr * 2;
                Hs[row * 68 + col]           = acc[mf][nf][0];
                Hs[row * 68 + col + 1]       = acc[mf][nf][1];
                Hs[(row + 8) * 68 + col]     = acc[mf][nf][2];
                Hs[(row + 8) * 68 + col + 1] = acc[mf][nf][3];
            }
        }
    }
    __syncthreads();
    if (w >= 8 && w < 16) {    // group 1 accumulates
        #pragma unroll
        for (int mf = 0; mf < 2; ++mf) {
            int row = wm * 32 + mf * 16 + lq;
            #pragma unroll
            for (int nf = 0; nf < 4; ++nf) {
                int col = wn * 32 + nf * 8 + lr * 2;
                Hs[row * 68 + col]           += acc[mf][nf][0];
                Hs[row * 68 + col + 1]       += acc[mf][nf][1];
                Hs[(row + 8) * 68 + col]     += acc[mf][nf][2];
                Hs[(row + 8) * 68 + col + 1] += acc[mf][nf][3];
            }
        }
    }
    __syncthreads();

    // Hs += (1+eps)*x  (vectorized from global)
    const float epsv = 1.0f + eps[0];
    if (tid < 512) {
        #pragma unroll
        for (int t = 0; t < 4; ++t) {
            int idx = tid + t * 512;          // 2048 float4 chunks
            int r = idx >> 4, c4 = idx & 15;
            float4 xv = ((const float4*)(xb + (size_t)(m0 + r) * FIN))[c4];
            float4* hp = (float4*)(Hs + r * 68 + c4 * 4);
            float4 hv = *hp;
            hv.x = fmaf(epsv, xv.x, hv.x);
            hv.y = fmaf(epsv, xv.y, hv.y);
            hv.z = fmaf(epsv, xv.z, hv.z);
            hv.w = fmaf(epsv, xv.w, hv.w);
            *hp = hv;
        }
    }
    if (tid < 256) cpwait<0>();   // weights group done (issuing threads)
    __syncthreads();

    // ---------- GEMM2: G = relu(Hs @ W1 + b1)  (128x128, K=64), 16 warps 4x4 ----------
    float* G = sm + G_BASE;             // [128][132]
    if (w < 16) {
        float acc2[2][4][4];
        #pragma unroll
        for (int i = 0; i < 2; ++i)
            #pragma unroll
            for (int j = 0; j < 4; ++j)
                #pragma unroll
                for (int k = 0; k < 4; ++k) acc2[i][j][k] = 0.f;

        const float* W1s = sm + W1_BASE;  // [64][136]
        #pragma unroll
        for (int ks = 0; ks < 8; ++ks) {
            int kk = ks * 8;
            unsigned a[2][4], bb[4][2];
            #pragma unroll
            for (int mf = 0; mf < 2; ++mf) {
                const float* ap = Hs + (wm * 32 + mf * 16 + lq) * 68 + kk + lr;
                a[mf][0] = f2tf(ap[0]);
                a[mf][1] = f2tf(ap[8 * 68]);
                a[mf][2] = f2tf(ap[4]);
                a[mf][3] = f2tf(ap[8 * 68 + 4]);
            }
            #pragma unroll
            for (int nf = 0; nf < 4; ++nf) {
                const float* bp = W1s + (kk + lr) * 136 + wq * 32 + nf * 8 + lq;
                bb[nf][0] = f2tf(bp[0]);
                bb[nf][1] = f2tf(bp[4 * 136]);
            }
            #pragma unroll
            for (int mf = 0; mf < 2; ++mf)
                #pragma unroll
                for (int nf = 0; nf < 4; ++nf)
                    mma8(acc2[mf][nf], a[mf], bb[nf]);
        }

        const float* b1s = sm + B1_BASE;
        #pragma unroll
        for (int mf = 0; mf < 2; ++mf) {
            int row = wm * 32 + mf * 16 + lq;
            #pragma unroll
            for (int nf = 0; nf < 4; ++nf) {
                int col = wq * 32 + nf * 8 + lr * 2;
                float bv0 = b1s[col], bv1 = b1s[col + 1];
                G[row * 132 + col]           = fmaxf(acc2[mf][nf][0] + bv0, 0.f);
                G[row * 132 + col + 1]       = fmaxf(acc2[mf][nf][1] + bv1, 0.f);
                G[(row + 8) * 132 + col]     = fmaxf(acc2[mf][nf][2] + bv0, 0.f);
                G[(row + 8) * 132 + col + 1] = fmaxf(acc2[mf][nf][3] + bv1, 0.f);
            }
        }
    }
    __syncthreads();

    // ---------- GEMM3: out = G @ W2 + b2, masked  (128x64, K=128), 16 warps 4x4 ----------
    if (w < 16) {
        float acc3[2][2][4];
        #pragma unroll
        for (int i = 0; i < 2; ++i)
            #pragma unroll
            for (int j = 0; j < 2; ++j)
                #pragma unroll
                for (int k = 0; k < 4; ++k) acc3[i][j][k] = 0.f;

        const float* W2s = sm + W2_BASE;  // [128][72]
        #pragma unroll
        for (int ks = 0; ks < 16; ++ks) {
            int kk = ks * 8;
            unsigned a[2][4], bb[2][2];
            #pragma unroll
            for (int mf = 0; mf < 2; ++mf) {
                const float* ap = G + (wm * 32 + mf * 16 + lq) * 132 + kk + lr;
                a[mf][0] = f2tf(ap[0]);
                a[mf][1] = f2tf(ap[8 * 132]);
                a[mf][2] = f2tf(ap[4]);
                a[mf][3] = f2tf(ap[8 * 132 + 4]);
            }
            #pragma unroll
            for (int nf = 0; nf < 2; ++nf) {
                const float* bp = W2s + (kk + lr) * 72 + wq * 16 + nf * 8 + lq;
                bb[nf][0] = f2tf(bp[0]);
                bb[nf][1] = f2tf(bp[4 * 72]);
            }
            #pragma unroll
            for (int mf = 0; mf < 2; ++mf)
                #pragma unroll
                for (int nf = 0; nf < 2; ++nf)
                    mma8(acc3[mf][nf], a[mf], bb[nf]);
        }

        auto mask_at = [&](int idx) -> bool {
            if (mmode == 0) return ((const int*)mask)[idx] != 0;
            if (mmode == 2) return ((const float*)mask)[idx] != 0.0f;
            return mask[idx] != 0;
        };

        const float* b2s = sm + B2_BASE;
        #pragma unroll
        for (int mf = 0; mf < 2; ++mf) {
            int row  = wm * 32 + mf * 16 + lq;
            int grow = m0 + row;
            bool mk0 = mask_at(b * NN + grow);
            bool mk1 = mask_at(b * NN + grow + 8);
            #pragma unroll
            for (int nf = 0; nf < 2; ++nf) {
                int col = wq * 16 + nf * 8 + lr * 2;
                float bv0 = b2s[col], bv1 = b2s[col + 1];
                float o0 = acc3[mf][nf][0] + bv0;
                float o1 = acc3[mf][nf][1] + bv1;
                float o2 = acc3[mf][nf][2] + bv0;
                float o3 = acc3[mf][nf][3] + bv1;
                float2* op0 = (float2*)(out + ((size_t)b * NN + grow) * 64 + col);
                float2* op1 = (float2*)(out + ((size_t)b * NN + grow + 8) * 64 + col);
                *op0 = mk0 ? make_float2(o0, o1) : make_float2(0.f, 0.f);
                *op1 = mk1 ? make_float2(o2, o3) : make_float2(0.f, 0.f);
            }
        }
    }
}

// ---- host side ----
typedef CUresult (*PFN_encodeTiled)(
    CUtensorMap*, CUtensorMapDataType, cuuint32_t, void*,
    const cuuint64_t*, const cuuint64_t*, const cuuint32_t*, const cuuint32_t*,
    CUtensorMapInterleave, CUtensorMapSwizzle, CUtensorMapL2promotion,
    CUtensorMapFloatOOBfill);

extern "C" void kernel_launch(void* const* d_in, const int* in_sizes, int n_in,
                              void* d_out, int out_size)
{
    // Identify inputs by element count (robust to metadata ordering).
    const float *x = 0, *adj = 0, *W1 = 0, *W2 = 0, *b1 = 0, *b2 = 0, *eps = 0;
    const unsigned char* mask = 0;
    for (int i = 0; i < n_in; ++i) {
        switch (in_sizes[i]) {
            case 64 * 1024 * 64:   x    = (const float*)d_in[i]; break;
            case 64 * 1024 * 1024: adj  = (const float*)d_in[i]; break;
            case 64 * 1024:        mask = (const unsigned char*)d_in[i]; break;
            case 64 * 128:         if (!W1) W1 = (const float*)d_in[i];
                                   else     W2 = (const float*)d_in[i]; break;
            case 128:              b1   = (const float*)d_in[i]; break;
            case 64:               b2   = (const float*)d_in[i]; break;
            case 1:                eps  = (const float*)d_in[i]; break;
            default: break;
        }
    }
    float* out = (float*)d_out;

    // Driver entry point via runtime API (no -lcuda link needed).
    static PFN_encodeTiled encode = nullptr;
    if (!encode) {
        void* fp = nullptr;
        cudaDriverEntryPointQueryResult qr;
        cudaGetDriverEntryPoint("cuTensorMapEncodeTiled", &fp, cudaEnableDefault, &qr);
        encode = (PFN_encodeTiled)fp;
    }

    CUtensorMap tm_adj{}, tm_x{};
    {
        cuuint64_t dims[3]    = {1024, 1024, 64};
        cuuint64_t strides[2] = {1024ull * 4, 1024ull * 1024 * 4};
        cuuint32_t box[3]     = {32, 128, 1};
        cuuint32_t es[3]      = {1, 1, 1};
        encode(&tm_adj, CU_TENSOR_MAP_DATA_TYPE_FLOAT32, 3, (void*)adj,
               dims, strides, box, es,
               CU_TENSOR_MAP_INTERLEAVE_NONE, CU_TENSOR_MAP_SWIZZLE_128B,
               CU_TENSOR_MAP_L2_PROMOTION_L2_128B, CU_TENSOR_MAP_FLOAT_OOB_FILL_NONE);
    }
    {
        cuuint64_t dims[3]    = {64, 1024, 64};
        cuuint64_t strides[2] = {64ull * 4, 1024ull * 64 * 4};
        cuuint32_t box[3]     = {32, 64, 1};
        cuuint32_t es[3]      = {1, 1, 1};
        encode(&tm_x, CU_TENSOR_MAP_DATA_TYPE_FLOAT32, 3, (void*)x,
               dims, strides, box, es,
               CU_TENSOR_MAP_INTERLEAVE_NONE, CU_TENSOR_MAP_SWIZZLE_128B,
               CU_TENSOR_MAP_L2_PROMOTION_L2_128B, CU_TENSOR_MAP_FLOAT_OOB_FILL_NONE);
    }

    cudaFuncSetAttribute(gin_fused_kernel,
                         cudaFuncAttributeMaxDynamicSharedMemorySize,
                         SMEM_FLOATS * (int)sizeof(float));
    gin_fused_kernel<<<512, NTHREADS, SMEM_FLOATS * sizeof(float)>>>(
        tm_adj, tm_x, x, mask, W1, b1, W2, b2, eps, out);
}

// round 11
// speedup vs baseline: 1.3360x; 1.0624x over previous
#include <cuda_runtime.h>
#include <cuda.h>
#include <cstdint>
#include <cstddef>

// Problem constants
#define NN    1024
#define FIN   64
#define NTHREADS 288          // 8 compute warps (4M x 2N) + 1 producer warp
#define TK    64
#define NST   3
#define NITER (NN / TK)       // 16

// ---- shared memory layout (floats) ----
// Ring: 3 stages x 48KB. Stage: adj k-half0 16KB | adj k-half1 16KB | x n-half0 8KB | x n-half1 8KB
#define STAGE_BYTES   49152
#define W1_BASE  36864                      // [64][136]
#define W2_BASE  45568                      // [128][72]
#define B1_BASE  54784
#define B2_BASE  54912
#define MBAR_FL  54976                      // 6 mbarriers (48B)
#define SMEM_FLOATS 54988                   // 219,952 bytes
#define TILE_BYTES 49152
// Post-mainloop overlays (ring dead):
#define HS_BASE 0                           // [128][68] = 8704 floats
#define G_BASE  8704                        // [128][132] = 16896 -> 25600 < 36864

__device__ __forceinline__ unsigned f2tf(float f) {
    unsigned u;
    asm("cvt.rna.tf32.f32 %0, %1;" : "=r"(u) : "f"(f));
    return u;
}

__device__ __forceinline__ void mma8(float* c, const unsigned* a, const unsigned* b) {
    asm volatile(
        "mma.sync.aligned.m16n8k8.row.col.f32.tf32.tf32.f32 "
        "{%0,%1,%2,%3},{%4,%5,%6,%7},{%8,%9},{%0,%1,%2,%3};"
        : "+f"(c[0]), "+f"(c[1]), "+f"(c[2]), "+f"(c[3])
        : "r"(a[0]), "r"(a[1]), "r"(a[2]), "r"(a[3]), "r"(b[0]), "r"(b[1]));
}

__device__ __forceinline__ void cp16(float* d, const float* s) {
    unsigned ds = (unsigned)__cvta_generic_to_shared(d);
    asm volatile("cp.async.cg.shared.global [%0], [%1], 16;" :: "r"(ds), "l"(s));
}
__device__ __forceinline__ void cpcommit() { asm volatile("cp.async.commit_group;"); }
template <int N> __device__ __forceinline__ void cpwait() {
    asm volatile("cp.async.wait_group %0;" :: "n"(N));
}

__device__ __forceinline__ void mbar_init(uint32_t mbar, uint32_t count) {
    asm volatile("mbarrier.init.shared.b64 [%0], %1;" :: "r"(mbar), "r"(count) : "memory");
}
__device__ __forceinline__ void mbar_expect_tx(uint32_t mbar, uint32_t bytes) {
    asm volatile("mbarrier.arrive.expect_tx.shared.b64 _, [%0], %1;" :: "r"(mbar), "r"(bytes) : "memory");
}
__device__ __forceinline__ void mbar_arrive(uint32_t mbar) {
    asm volatile("mbarrier.arrive.shared.b64 _, [%0];" :: "r"(mbar) : "memory");
}
__device__ __forceinline__ void mbar_wait(uint32_t mbar, uint32_t parity) {
    asm volatile(
        "{\n\t.reg .pred P;\n\t"
        "WL_%=:\n\t"
        "mbarrier.try_wait.parity.acquire.cta.shared::cta.b64 P, [%0], %1, 0x989680;\n\t"
        "@P bra.uni WD_%=;\n\t"
        "bra.uni WL_%=;\n\t"
        "WD_%=:\n\t}"
        :: "r"(mbar), "r"(parity) : "memory");
}

__device__ __forceinline__ void tma3d(uint32_t smem_dst, const CUtensorMap* map,
                                      int c0, int c1, int c2, uint32_t mbar) {
    asm volatile(
        "cp.async.bulk.tensor.3d.shared::cta.global.tile.mbarrier::complete_tx::bytes "
        "[%0], [%1, {%2, %3, %4}], [%5];"
        :: "r"(smem_dst), "l"(map), "r"(c0), "r"(c1), "r"(c2), "r"(mbar) : "memory");
}

extern __shared__ float sm[];

__global__ void __launch_bounds__(NTHREADS, 1) gin_fused_kernel(
    const __grid_constant__ CUtensorMap tma_adj,
    const __grid_constant__ CUtensorMap tma_x,
    const float* __restrict__ x,
    const unsigned char* __restrict__ mask,
    const float* __restrict__ W1, const float* __restrict__ b1,
    const float* __restrict__ W2, const float* __restrict__ b2,
    const float* __restrict__ eps, float* __restrict__ out)
{
    const int tid  = threadIdx.x;
    const int b    = blockIdx.x >> 3;
    const int m0   = (blockIdx.x & 7) * 128;
    const int lane = tid & 31;
    const int w    = tid >> 5;    // 0..8 ; warp 8 = producer
    const int wm   = w >> 1;      // 0..3 (compute warps)
    const int wn   = w & 1;       // 0..1
    const int lq   = lane >> 2;
    const int lr   = lane & 3;

    const float* xb = x + (size_t)b * NN * FIN;

    uint32_t smem_u32;
    asm("{ .reg .u64 t; cvta.to.shared.u64 t, %1; cvt.u32.u64 %0, t; }"
        : "=r"(smem_u32) : "l"(sm));
    const uint32_t mb_full0  = smem_u32 + MBAR_FL * 4;
    const uint32_t mb_empty0 = mb_full0 + 24;

    // ---------- inline mask-dtype probe (first 4 KB) ----------
    // mode: 0=int32, 1=uint8/bool, 2=float32
    int gt1 = 0, nzoff = 0;
    if (tid < 256) {
        uint4 u = ((const uint4*)mask)[tid];
        unsigned words[4] = {u.x, u.y, u.z, u.w};
        #pragma unroll
        for (int wi = 0; wi < 4; ++wi) {
            #pragma unroll
            for (int bi = 0; bi < 4; ++bi) {
                unsigned byte = (words[wi] >> (bi * 8)) & 0xFF;
                if (byte > 1) gt1 = 1;
                if (byte != 0 && ((wi * 4 + bi) & 3) != 0) nzoff = 1;
            }
        }
    }
    const int any_gt1   = __syncthreads_or(gt1);
    const int any_nzoff = __syncthreads_or(nzoff);
    const int mmode = any_gt1 ? 2 : (any_nzoff ? 1 : 0);

    // ---------- mbarrier init ----------
    if (tid == 0) {
        #pragma unroll
        for (int s = 0; s < NST; ++s) {
            mbar_init(mb_full0  + s * 8, 1);    // producer elect thread
            mbar_init(mb_empty0 + s * 8, 256);  // all compute threads
        }
    }

    // ---------- weights prologue (cp.async, waited after mainloop) ----------
    if (tid < 256) {
        #pragma unroll
        for (int t = 0; t < 8; ++t) {              // W1: 64x128 -> [64][136]
            int c = tid + t * 256;
            int r = c >> 5, cc = c & 31;
            cp16(sm + W1_BASE + r * 136 + cc * 4, W1 + r * 128 + cc * 4);
        }
        #pragma unroll
        for (int t = 0; t < 8; ++t) {              // W2: 128x64 -> [128][72]
            int c = tid + t * 256;
            int r = c >> 4, cc = c & 15;
            cp16(sm + W2_BASE + r * 72 + cc * 4, W2 + r * 64 + cc * 4);
        }
        if (tid < 32) cp16(sm + B1_BASE + tid * 4, b1 + tid * 4);
        if (tid < 16) cp16(sm + B2_BASE + tid * 4, b2 + tid * 4);
        cpcommit();
    }
    __syncthreads();   // mbar init visible before any TMA

    // ---------- GEMM1: agg = adj[b] @ x[b]  (M=128, N=64, K=1024) ----------
    // B physical-feat permutation sigma(nf, j) = (j&3) | (nf<<2) | ((j>>2)<<4)
    // makes every B fragment LDS bank-conflict-free under the TMA SW128 swizzle
    // (lane bits land at word bits {0,1}=j0j1, {2,3}=nf^lr, {4}=j2 -> 32 distinct banks).
    float acc[2][4][4];
    #pragma unroll
    for (int i = 0; i < 2; ++i)
        #pragma unroll
        for (int j = 0; j < 4; ++j)
            #pragma unroll
            for (int k = 0; k < 4; ++k) acc[i][j][k] = 0.f;

    if (w == 8) {
        if (lane == 0) {
            for (int it = 0; it < NITER; ++it) {
                const int s = it % NST, u = it / NST;
                if (it >= NST) mbar_wait(mb_empty0 + s * 8, (u - 1) & 1);
                const uint32_t full = mb_full0 + s * 8;
                mbar_expect_tx(full, TILE_BYTES);
                const uint32_t sb = smem_u32 + s * STAGE_BYTES;
                const int k0 = it * TK;
                tma3d(sb,         &tma_adj, k0,      m0, b, full);  // adj k-half 0
                tma3d(sb + 16384, &tma_adj, k0 + 32, m0, b, full);  // adj k-half 1
                tma3d(sb + 32768, &tma_x,   0,       k0, b, full);  // x  n-half 0
                tma3d(sb + 40960, &tma_x,   32,      k0, b, full);  // x  n-half 1
            }
        }
    } else {
        const uint32_t xorA = (uint32_t)lq << 4;   // SW128: row%8 == lq
        for (int it = 0; it < NITER; ++it) {
            const int s = it % NST, u = it / NST;
            mbar_wait(mb_full0 + s * 8, u & 1);

            const char* stage = (const char*)sm + s * STAGE_BYTES;
            const char* Bh    = stage + 32768 + wn * 8192;  // this warp's x n-half
            #pragma unroll
            for (int ks = 0; ks < TK / 8; ++ks) {
                const int kk = ks * 8;
                const char* Ah = stage + ((kk >> 5) << 14);  // 16KB per adj k-half
                const int kl = (kk & 31) + lr;
                unsigned a[2][4], bb[4][2];
                #pragma unroll
                for (int mf = 0; mf < 2; ++mf) {
                    const uint32_t r0 = (uint32_t)(wm * 32 + mf * 16 + lq) * 128;
                    const uint32_t r1 = r0 + 8 * 128;
                    a[mf][0] = f2tf(*(const float*)(Ah + r0 + (((uint32_t)kl << 2) ^ xorA)));
                    a[mf][1] = f2tf(*(const float*)(Ah + r1 + (((uint32_t)kl << 2) ^ xorA)));
                    a[mf][2] = f2tf(*(const float*)(Ah + r0 + (((uint32_t)(kl + 4) << 2) ^ xorA)));
                    a[mf][3] = f2tf(*(const float*)(Ah + r1 + (((uint32_t)(kl + 4) << 2) ^ xorA)));
                }
                const uint32_t kr0 = (uint32_t)(kk + lr) * 128;
                const uint32_t kr1 = kr0 + 4 * 128;
                const uint32_t xb0 = (uint32_t)lr << 4;
                const uint32_t xb1 = (uint32_t)(lr + 4) << 4;
                #pragma unroll
                for (int nf = 0; nf < 4; ++nf) {
                    // permuted physical feat for logical col j = lq
                    const uint32_t perm = (uint32_t)((lq & 3) | (nf << 2) | ((lq >> 2) << 4));
                    const uint32_t nl = perm << 2;
                    bb[nf][0] = f2tf(*(const float*)(Bh + kr0 + (nl ^ xb0)));
                    bb[nf][1] = f2tf(*(const float*)(Bh + kr1 + (nl ^ xb1)));
                }
                #pragma unroll
                for (int mf = 0; mf < 2; ++mf)
                    #pragma unroll
                    for (int nf = 0; nf < 4; ++nf)
                        mma8(acc[mf][nf], a[mf], bb[nf]);
            }
            mbar_arrive(mb_empty0 + s * 8);
        }
    }
    __syncthreads();   // ring fully drained; safe to overlay

    // ---------- epilogue 1: Hs = agg (un-permute cols) ----------
    float* Hs = sm + HS_BASE;  // [128][68]
    if (w < 8) {
        const int c0l = lr * 2;          // logical col pair start
        #pragma unroll
        for (int mf = 0; mf < 2; ++mf) {
            int row = wm * 32 + mf * 16 + lq;
            #pragma unroll
            for (int nf = 0; nf < 4; ++nf) {
                int p0  = (c0l & 3) | (nf << 2) | ((c0l >> 2) << 4);   // physical feat
                int col = wn * 32 + p0;
                Hs[row * 68 + col]           = acc[mf][nf][0];
                Hs[row * 68 + col + 1]       = acc[mf][nf][1];
                Hs[(row + 8) * 68 + col]     = acc[mf][nf][2];
                Hs[(row + 8) * 68 + col + 1] = acc[mf][nf][3];
            }
        }
    }
    __syncthreads();

    // Hs += (1+eps)*x  (vectorized from global)
    const float epsv = 1.0f + eps[0];
    if (tid < 256) {
        #pragma unroll
        for (int t = 0; t < 8; ++t) {
            int idx = tid + t * 256;          // 2048 float4 chunks
            int r = idx >> 4, c4 = idx & 15;
            float4 xv = ((const float4*)(xb + (size_t)(m0 + r) * FIN))[c4];
            float4* hp = (float4*)(Hs + r * 68 + c4 * 4);
            float4 hv = *hp;
            hv.x = fmaf(epsv, xv.x, hv.x);
            hv.y = fmaf(epsv, xv.y, hv.y);
            hv.z = fmaf(epsv, xv.z, hv.z);
            hv.w = fmaf(epsv, xv.w, hv.w);
            *hp = hv;
        }
        cpwait<0>();    // weights group done
    }
    __syncthreads();

    // ---------- GEMM2: G = relu(Hs @ W1 + b1)  (128x128, K=64), 8 warps 4x2 ----------
    float* G = sm + G_BASE;             // [128][132]
    if (w < 8) {
        float acc2[2][8][4];
        #pragma unroll
        for (int i = 0; i < 2; ++i)
            #pragma unroll
            for (int j = 0; j < 8; ++j)
                #pragma unroll
                for (int k = 0; k < 4; ++k) acc2[i][j][k] = 0.f;

        const float* W1s = sm + W1_BASE;  // [64][136]
        #pragma unroll
        for (int ks = 0; ks < 8; ++ks) {
            int kk = ks * 8;
            unsigned a[2][4], bb[8][2];
            #pragma unroll
            for (int mf = 0; mf < 2; ++mf) {
                const float* ap = Hs + (wm * 32 + mf * 16 + lq) * 68 + kk + lr;
                a[mf][0] = f2tf(ap[0]);
                a[mf][1] = f2tf(ap[8 * 68]);
                a[mf][2] = f2tf(ap[4]);
                a[mf][3] = f2tf(ap[8 * 68 + 4]);
            }
            #pragma unroll
            for (int nf = 0; nf < 8; ++nf) {
                const float* bp = W1s + (kk + lr) * 136 + wn * 64 + nf * 8 + lq;
                bb[nf][0] = f2tf(bp[0]);
                bb[nf][1] = f2tf(bp[4 * 136]);
            }
            #pragma unroll
            for (int mf = 0; mf < 2; ++mf)
                #pragma unroll
                for (int nf = 0; nf < 8; ++nf)
                    mma8(acc2[mf][nf], a[mf], bb[nf]);
        }

        const float* b1s = sm + B1_BASE;
        #pragma unroll
        for (int mf = 0; mf < 2; ++mf) {
            int row = wm * 32 + mf * 16 + lq;
            #pragma unroll
            for (int nf = 0; nf < 8; ++nf) {
                int col = wn * 64 + nf * 8 + lr * 2;
                float bv0 = b1s[col], bv1 = b1s[col + 1];
                G[row * 132 + col]           = fmaxf(acc2[mf][nf][0] + bv0, 0.f);
                G[row * 132 + col + 1]       = fmaxf(acc2[mf][nf][1] + bv1, 0.f);
                G[(row + 8) * 132 + col]     = fmaxf(acc2[mf][nf][2] + bv0, 0.f);
                G[(row + 8) * 132 + col + 1] = fmaxf(acc2[mf][nf][3] + bv1, 0.f);
            }
        }
    }
    __syncthreads();

    // ---------- GEMM3: out = G @ W2 + b2, masked  (128x64, K=128), 8 warps 4x2 ----------
    if (w < 8) {
        float acc3[2][4][4];
        #pragma unroll
        for (int i = 0; i < 2; ++i)
            #pragma unroll
            for (int j = 0; j < 4; ++j)
                #pragma unroll
                for (int k = 0; k < 4; ++k) acc3[i][j][k] = 0.f;

        const float* W2s = sm + W2_BASE;  // [128][72]
        #pragma unroll
        for (int ks = 0; ks < 16; ++ks) {
            int kk = ks * 8;
            unsigned a[2][4], bb[4][2];
            #pragma unroll
            for (int mf = 0; mf < 2; ++mf) {
                const float* ap = G + (wm * 32 + mf * 16 + lq) * 132 + kk + lr;
                a[mf][0] = f2tf(ap[0]);
                a[mf][1] = f2tf(ap[8 * 132]);
                a[mf][2] = f2tf(ap[4]);
                a[mf][3] = f2tf(ap[8 * 132 + 4]);
            }
            #pragma unroll
            for (int nf = 0; nf < 4; ++nf) {
                const float* bp = W2s + (kk + lr) * 72 + wn * 32 + nf * 8 + lq;
                bb[nf][0] = f2tf(bp[0]);
                bb[nf][1] = f2tf(bp[4 * 72]);
            }
            #pragma unroll
            for (int mf = 0; mf < 2; ++mf)
                #pragma unroll
                for (int nf = 0; nf < 4; ++nf)
                    mma8(acc3[mf][nf], a[mf], bb[nf]);
        }

        auto mask_at = [&](int idx) -> bool {
            if (mmode == 0) return ((const int*)mask)[idx] != 0;
            if (mmode == 2) return ((const float*)mask)[idx] != 0.0f;
            return mask[idx] != 0;
        };

        const float* b2s = sm + B2_BASE;
        #pragma unroll
        for (int mf = 0; mf < 2; ++mf) {
            int row  = wm * 32 + mf * 16 + lq;
            int grow = m0 + row;
            bool mk0 = mask_at(b * NN + grow);
            bool mk1 = mask_at(b * NN + grow + 8);
            #pragma unroll
            for (int nf = 0; nf < 4; ++nf) {
                int col = wn * 32 + nf * 8 + lr * 2;
                float bv0 = b2s[col], bv1 = b2s[col + 1];
                float o0 = acc3[mf][nf][0] + bv0;
                float o1 = acc3[mf][nf][1] + bv1;
                float o2 = acc3[mf][nf][2] + bv0;
                float o3 = acc3[mf][nf][3] + bv1;
                float2* op0 = (float2*)(out + ((size_t)b * NN + grow) * 64 + col);
                float2* op1 = (float2*)(out + ((size_t)b * NN + grow + 8) * 64 + col);
                *op0 = mk0 ? make_float2(o0, o1) : make_float2(0.f, 0.f);
                *op1 = mk1 ? make_float2(o2, o3) : make_float2(0.f, 0.f);
            }
        }
    }
}

// ---- host side ----
typedef CUresult (*PFN_encodeTiled)(
    CUtensorMap*, CUtensorMapDataType, cuuint32_t, void*,
    const cuuint64_t*, const cuuint64_t*, const cuuint32_t*, const cuuint32_t*,
    CUtensorMapInterleave, CUtensorMapSwizzle, CUtensorMapL2promotion,
    CUtensorMapFloatOOBfill);

extern "C" void kernel_launch(void* const* d_in, const int* in_sizes, int n_in,
                              void* d_out, int out_size)
{
    // Identify inputs by element count (robust to metadata ordering).
    const float *x = 0, *adj = 0, *W1 = 0, *W2 = 0, *b1 = 0, *b2 = 0, *eps = 0;
    const unsigned char* mask = 0;
    for (int i = 0; i < n_in; ++i) {
        switch (in_sizes[i]) {
            case 64 * 1024 * 64:   x    = (const float*)d_in[i]; break;
            case 64 * 1024 * 1024: adj  = (const float*)d_in[i]; break;
            case 64 * 1024:        mask = (const unsigned char*)d_in[i]; break;
            case 64 * 128:         if (!W1) W1 = (const float*)d_in[i];
                                   else     W2 = (const float*)d_in[i]; break;
            case 128:              b1   = (const float*)d_in[i]; break;
            case 64:               b2   = (const float*)d_in[i]; break;
            case 1:                eps  = (const float*)d_in[i]; break;
            default: break;
        }
    }
    float* out = (float*)d_out;

    // Driver entry point via runtime API (no -lcuda link needed).
    static PFN_encodeTiled encode = nullptr;
    if (!encode) {
        void* fp = nullptr;
        cudaDriverEntryPointQueryResult qr;
        cudaGetDriverEntryPoint("cuTensorMapEncodeTiled", &fp, cudaEnableDefault, &qr);
        encode = (PFN_encodeTiled)fp;
    }

    CUtensorMap tm_adj{}, tm_x{};
    {
        cuuint64_t dims[3]    = {1024, 1024, 64};
        cuuint64_t strides[2] = {1024ull * 4, 1024ull * 1024 * 4};
        cuuint32_t box[3]     = {32, 128, 1};
        cuuint32_t es[3]      = {1, 1, 1};
        encode(&tm_adj, CU_TENSOR_MAP_DATA_TYPE_FLOAT32, 3, (void*)adj,
               dims, strides, box, es,
               CU_TENSOR_MAP_INTERLEAVE_NONE, CU_TENSOR_MAP_SWIZZLE_128B,
               CU_TENSOR_MAP_L2_PROMOTION_L2_128B, CU_TENSOR_MAP_FLOAT_OOB_FILL_NONE);
    }
    {
        cuuint64_t dims[3]    = {64, 1024, 64};
        cuuint64_t strides[2] = {64ull * 4, 1024ull * 64 * 4};
        cuuint32_t box[3]     = {32, 64, 1};
        cuuint32_t es[3]      = {1, 1, 1};
        encode(&tm_x, CU_TENSOR_MAP_DATA_TYPE_FLOAT32, 3, (void*)x,
               dims, strides, box, es,
               CU_TENSOR_MAP_INTERLEAVE_NONE, CU_TENSOR_MAP_SWIZZLE_128B,
               CU_TENSOR_MAP_L2_PROMOTION_L2_128B, CU_TENSOR_MAP_FLOAT_OOB_FILL_NONE);
    }

    cudaFuncSetAttribute(gin_fused_kernel,
                         cudaFuncAttributeMaxDynamicSharedMemorySize,
                         SMEM_FLOATS * (int)sizeof(float));
    gin_fused_kernel<<<512, NTHREADS, SMEM_FLOATS * sizeof(float)>>>(
        tm_adj, tm_x, x, mask, W1, b1, W2, b2, eps, out);
}